// round 4
// baseline (speedup 1.0000x reference)
#include <cuda_runtime.h>

// LoCon1d: out[b][o][s] = bias[o][s] + sum_{c,k} in[b][c][s+k-1] * w[o][c][s][k]
// Shapes: input (16, 64, 1024), weight (64, 64, 1024, 3), bias (64, 1024), out (16, 64, 1024)
// Zero padding at s boundaries (PAD = 1).

#define CIN  64
#define COUT 64
#define SLEN 1024
#define BATCH 16
#define KW   3

#define S_PER_THREAD 4
#define B_PER_THREAD 8
#define TPB 128  // threads per block; each thread covers 4 s-positions for 8 batches

__global__ __launch_bounds__(TPB)
void locon1d_kernel(const float* __restrict__ input,
                    const float* __restrict__ weight,
                    const float* __restrict__ bias,
                    float* __restrict__ out)
{
    const int sg = blockIdx.x * TPB + threadIdx.x;   // s-group id, 0..255
    const int s0 = sg * S_PER_THREAD;                // multiple of 4
    const int o  = blockIdx.y;                       // cout
    const int b0 = blockIdx.z * B_PER_THREAD;        // batch base

    float acc[B_PER_THREAD][S_PER_THREAD];
#pragma unroll
    for (int bb = 0; bb < B_PER_THREAD; bb++)
#pragma unroll
        for (int i = 0; i < S_PER_THREAD; i++)
            acc[bb][i] = 0.0f;

    // weight base for (o, c=0, s0, k=0); per-c stride = SLEN*KW = 3072 floats
    const float* wbase = weight + ((size_t)o * CIN * SLEN + (size_t)s0) * KW;
    // input base for (b0, c=0, s0); per-c stride = SLEN, per-b stride = CIN*SLEN
    const float* ibase = input + ((size_t)b0 * CIN) * SLEN + s0;

    const bool has_left  = (s0 > 0);
    const bool has_right = (s0 + S_PER_THREAD < SLEN);

    for (int c = 0; c < CIN; c++) {
        // 12 contiguous, 16B-aligned weight floats: w[(s0+i)*3 + k], i=0..3, k=0..2
        const float4* wp = (const float4*)(wbase + (size_t)c * (SLEN * KW));
        float4 w0 = wp[0];
        float4 w1 = wp[1];
        float4 w2 = wp[2];
        float w[12] = { w0.x, w0.y, w0.z, w0.w,
                        w1.x, w1.y, w1.z, w1.w,
                        w2.x, w2.y, w2.z, w2.w };

        const float* ip = ibase + (size_t)c * SLEN;
#pragma unroll
        for (int bb = 0; bb < B_PER_THREAD; bb++) {
            const float* ib = ip + (size_t)bb * (CIN * SLEN);
            float4 x = *(const float4*)ib;                      // s0..s0+3
            float e0 = has_left  ? ib[-1]            : 0.0f;    // s0-1
            float e5 = has_right ? ib[S_PER_THREAD]  : 0.0f;    // s0+4
            float e[6] = { e0, x.x, x.y, x.z, x.w, e5 };
#pragma unroll
            for (int i = 0; i < S_PER_THREAD; i++) {
                // out position s = s0+i uses e[i],e[i+1],e[i+2] and w[3i..3i+2]
                acc[bb][i] = fmaf(e[i],     w[3*i],
                             fmaf(e[i + 1], w[3*i + 1],
                             fmaf(e[i + 2], w[3*i + 2], acc[bb][i])));
            }
        }
    }

    // add bias and store (vectorized, coalesced)
    float4 bv = *(const float4*)(bias + (size_t)o * SLEN + s0);
    const float bz[4] = { bv.x, bv.y, bv.z, bv.w };
#pragma unroll
    for (int bb = 0; bb < B_PER_THREAD; bb++) {
        float4 r;
        r.x = acc[bb][0] + bz[0];
        r.y = acc[bb][1] + bz[1];
        r.z = acc[bb][2] + bz[2];
        r.w = acc[bb][3] + bz[3];
        *(float4*)(out + ((size_t)(b0 + bb) * COUT + o) * SLEN + s0) = r;
    }
}

extern "C" void kernel_launch(void* const* d_in, const int* in_sizes, int n_in,
                              void* d_out, int out_size)
{
    const float* input  = (const float*)d_in[0];  // (16, 64, 1024)
    const float* weight = (const float*)d_in[1];  // (64, 64, 1024, 3)
    const float* bias   = (const float*)d_in[2];  // (64, 1024)
    float* out = (float*)d_out;                   // (16, 64, 1024)

    dim3 grid(SLEN / S_PER_THREAD / TPB,  // 2  (s tiles)
              COUT,                        // 64 (cout)
              BATCH / B_PER_THREAD);       // 2  (batch halves)
    locon1d_kernel<<<grid, TPB>>>(input, weight, bias, out);
}